// round 14
// baseline (speedup 1.0000x reference)
#include <cuda_runtime.h>
#include <cuda_fp16.h>
#include <cstdint>

#define BB 4
#define LL 512
#define DD 768
#define WW 12
#define TWOD 1536
#define THREED 2304
#define BL 2048
#define MOUT 24576
#define WD 9216

// ---- scratch (device globals; no allocation allowed) ----
__device__ __align__(16) __half g_hh[(long)BL*DD];                // h fp16
__device__ __align__(16) __half g_pwh[(long)TWOD*DD];             // proj_w fp16
__device__ __align__(16) __half g_owh[(long)DD*THREED];           // out_w fp16
__device__ __align__(16) __half g_cwth[(long)WD*DD];              // conv_w transposed fp16
__device__ __align__(16) __half g_ph[(long)BL*TWOD];              // relu(proj) fp16
__device__ __align__(16) __half g_G[(long)BL*WD];                 // conv contributions fp16
__device__ __align__(16) __half g_ch[(long)MOUT*DD];              // relu(cumsum) fp16
__device__ __align__(16) float  g_SA[(long)BL*DD], g_SB[(long)BL*DD];
__device__ int g_is64;

// ---- PTX helpers (baseline ISA only; valid on compute_103) ----
__device__ __forceinline__ uint32_t smem_u32(const void* p) {
    uint32_t a;
    asm("{ .reg .u64 t; cvta.to.shared.u64 t, %1; cvt.u32.u64 %0, t; }" : "=r"(a) : "l"(p));
    return a;
}
__device__ __forceinline__ void cp16(uint32_t dst, const void* src) {
    asm volatile("cp.async.cg.shared.global [%0], [%1], 16;" :: "r"(dst), "l"(src));
}
#define CP_COMMIT() asm volatile("cp.async.commit_group;" ::: "memory")
#define CP_WAIT1()  asm volatile("cp.async.wait_group 1;" ::: "memory")

#define LDSM4(r, addr) \
    asm volatile("ldmatrix.sync.aligned.m8n8.x4.shared.b16 {%0,%1,%2,%3}, [%4];" \
        : "=r"((r)[0]), "=r"((r)[1]), "=r"((r)[2]), "=r"((r)[3]) : "r"(addr))

#define MMA16816(acc, a, b0, b1) \
    asm volatile("mma.sync.aligned.m16n8k16.row.col.f32.f16.f16.f32 " \
        "{%0,%1,%2,%3}, {%4,%5,%6,%7}, {%8,%9}, {%0,%1,%2,%3};" \
        : "+f"((acc)[0]), "+f"((acc)[1]), "+f"((acc)[2]), "+f"((acc)[3]) \
        : "r"((a)[0]), "r"((a)[1]), "r"((a)[2]), "r"((a)[3]), "r"(b0), "r"(b1))

// ---------------------------------------------------------------------------
__global__ void detect_idx_kernel(const int* __restrict__ p, int nwords) {
    __shared__ int any;
    if (threadIdx.x == 0) any = 0;
    __syncthreads();
    int found = 0;
    for (int i = threadIdx.x; 2 * i + 1 < nwords; i += blockDim.x)
        found |= (p[2 * i + 1] != 0);
    if (found) atomicOr(&any, 1);
    __syncthreads();
    if (threadIdx.x == 0) g_is64 = (any == 0) ? 1 : 0;
}

// fp32 -> fp16, vectorized (n divisible by 4)
__global__ void tofp16v4_kernel(const float4* __restrict__ x, __half2* __restrict__ y, long n4) {
    long i = (long)blockIdx.x * blockDim.x + threadIdx.x;
    if (i >= n4) return;
    float4 v = x[i];
    y[2 * i]     = __floats2half2_rn(v.x, v.y);
    y[2 * i + 1] = __floats2half2_rn(v.z, v.w);
}

// conv_w [o,c,k] -> cwt [k*DD+o][c] fp16, half2 stores
__global__ void transpose_cw_kernel(const float* __restrict__ cw, __half2* __restrict__ th2) {
    int idx = blockIdx.x * blockDim.x + threadIdx.x;   // over DD*DD/2
    if (idx >= DD * (DD / 2)) return;
    int o = idx / (DD / 2), c2 = idx % (DD / 2);
    const float* s0 = cw + ((long)o * DD + 2 * c2) * WW;
    const float* s1 = s0 + WW;
#pragma unroll
    for (int k = 0; k < WW; k++)
        th2[((long)k * DD + o) * (DD / 2) + c2] = __floats2half2_rn(s0[k], s1[k]);
}

// shifted cumsum of G (fp16, fp32 accum) + relu -> fp16, half2 vectorized
__global__ void cumsum_relu_kernel(const __half2* __restrict__ G2, __half2* __restrict__ ch2) {
    long id = (long)blockIdx.x * blockDim.x + threadIdx.x;   // over BL*DD/2
    if (id >= (long)BL * (DD / 2)) return;
    int o2 = (int)(id % (DD / 2));
    int bl = (int)(id / (DD / 2));
    int l  = bl % LL;
    int bt = bl - l;
    float sx = 0.f, sy = 0.f;
#pragma unroll
    for (int k = 0; k < WW; k++) {
        int t = l + k;
        if (t < LL) {
            float2 g = __half22float2(G2[((long)(bt + t) * WW + k) * (DD / 2) + o2]);
            sx += g.x; sy += g.y;
        }
        ch2[((long)bl * WW + k) * (DD / 2) + o2] =
            __floats2half2_rn(fmaxf(sx, 0.f), fmaxf(sy, 0.f));
    }
}

// ---------------------------------------------------------------------------
// fp16 GEMM via mma.sync:  C[m,n] = sum_k A[m,k]*B[n,k]   (fp32 acc)
// CTA tile 128x128, BK=96, 8 warps (2M x 4N), warp tile 64x32.
// 2-stage double buffer, 2 syncs/iter, 96 MMAs per sync interval. 2 CTAs/SM.
// EPI: 0=fp32 store, 1=bias+relu->fp16, 2=final fused fp32, 3=plain fp16 store
// blockIdx.z==1 switches to (A2,B2,C2) — used to batch SA/SB in one launch.
#define BKK 96
#define ROWB 208                // 96*2 + 16 pad
#define TILEB (128*ROWB)        // 26624
#define STAGEB (2*TILEB)        // 53248 (A + B)
#define SMEMB (2*STAGEB)        // 106496

template <int EPI>
__global__ __launch_bounds__(256, 2)
void gemm_mma(const __half* __restrict__ Ap, int lda,
              const __half* __restrict__ Bp, int ldb,
              float* __restrict__ Cp, __half* __restrict__ Cf16,
              int ldc, int K,
              const float* __restrict__ bias,
              const float* __restrict__ SA, const float* __restrict__ SB,
              const int* __restrict__ span32,
              const __half* A2, const __half* B2, float* C2) {
    extern __shared__ char smem[];
    const uint32_t sbase = smem_u32(smem);
    const int tid = threadIdx.x, lane = tid & 31, wid = tid >> 5;
    const int wm = wid & 1, wn = wid >> 1;           // 2 x 4 warp grid
    const int m0 = blockIdx.y * 128, n0 = blockIdx.x * 128;
    const int NIT = K / BKK;

    const __half* A = Ap;
    const __half* B = Bp;
    float* C = Cp;
    if (blockIdx.z) { A = A2; B = B2; C = C2; }

    const char* gA = (const char*)(A + (long)m0 * lda);
    const char* gB = (const char*)(B + (long)n0 * ldb);
    const long ldaB = (long)lda * 2, ldbB = (long)ldb * 2;

    // per stage: tile = 128 rows x 192B (12 chunks of 16B). 2 threads/row, 6 chunks each.
    const int lr  = tid >> 1;                 // row 0..127
    const int lc0 = (tid & 1) * 6;            // chunk base 0 or 6

    auto issue_load = [&](int it) {
        const long k0b = (long)it * (BKK * 2);       // BK cols * 2B
        const uint32_t st = sbase + (it & 1) * STAGEB;
        const uint32_t rowA = st + lr * ROWB;
        const char* srcA = gA + (long)lr * ldaB + k0b;
#pragma unroll
        for (int c = 0; c < 6; c++)
            cp16(rowA + (lc0 + c) * 16, srcA + (lc0 + c) * 16);
        const uint32_t rowBs = st + TILEB + lr * ROWB;
        const char* srcB = gB + (long)lr * ldbB + k0b;
#pragma unroll
        for (int c = 0; c < 6; c++)
            cp16(rowBs + (lc0 + c) * 16, srcB + (lc0 + c) * 16);
    };

    float acc[4][4][4];
#pragma unroll
    for (int i = 0; i < 4; i++)
#pragma unroll
        for (int j = 0; j < 4; j++)
#pragma unroll
            for (int v = 0; v < 4; v++) acc[i][j][v] = 0.f;

    issue_load(0); CP_COMMIT();

    const uint32_t a_lane_off = (uint32_t)((wm * 64 + (lane & 15)) * ROWB + (lane >> 4) * 16);
    const uint32_t b_lane_off = (uint32_t)((wn * 32 + (lane & 15)) * ROWB + (lane >> 4) * 16);

    for (int it = 0; it < NIT; it++) {
        if (it + 1 < NIT) issue_load(it + 1);
        CP_COMMIT();
        CP_WAIT1();
        __syncthreads();

        const uint32_t st = sbase + (it & 1) * STAGEB;
#pragma unroll
        for (int ks = 0; ks < BKK / 16; ks++) {      // 6 sub-steps
            uint32_t a[4][4];
#pragma unroll
            for (int mt = 0; mt < 4; mt++)
                LDSM4(a[mt], st + a_lane_off + mt * 16 * ROWB + ks * 32);
            uint32_t b[2][4];
#pragma unroll
            for (int nb = 0; nb < 2; nb++)
                LDSM4(b[nb], st + TILEB + b_lane_off + nb * 16 * ROWB + ks * 32);
#pragma unroll
            for (int mt = 0; mt < 4; mt++)
#pragma unroll
                for (int nt = 0; nt < 4; nt++) {
                    const int nb = nt >> 1, sel = nt & 1;
                    MMA16816(acc[mt][nt], a[mt], b[nb][sel], b[nb][sel + 2]);
                }
        }
        __syncthreads();
    }

    // ---- epilogue ----
    const int qrow = lane >> 2, qcol = (lane & 3) * 2;
    const int is64 = (EPI == 2) ? g_is64 : 0;

#pragma unroll
    for (int mt = 0; mt < 4; mt++) {
        const int r0 = m0 + wm * 64 + mt * 16 + qrow;
        const int r1 = r0 + 8;

        const float *sa0 = nullptr, *sb0 = nullptr, *sa1 = nullptr, *sb1 = nullptr;
        if (EPI == 2) {
            int sw0, ew0, sw1, ew1;
            if (is64) {
                sw0 = span32[(long)r0 * 4]; ew0 = span32[(long)r0 * 4 + 2];
                sw1 = span32[(long)r1 * 4]; ew1 = span32[(long)r1 * 4 + 2];
            } else {
                sw0 = span32[(long)r0 * 2]; ew0 = span32[(long)r0 * 2 + 1];
                sw1 = span32[(long)r1 * 2]; ew1 = span32[(long)r1 * 2 + 1];
            }
            sw0 = min(max(sw0, 0), LL - 1); ew0 = min(max(ew0, 0), LL - 1);
            sw1 = min(max(sw1, 0), LL - 1); ew1 = min(max(ew1, 0), LL - 1);
            int boff = (r0 / (LL * WW)) * LL;   // r0, r1 always in same batch (16 | LL*WW)
            sa0 = SA + (long)(boff + sw0) * DD; sb0 = SB + (long)(boff + ew0) * DD;
            sa1 = SA + (long)(boff + sw1) * DD; sb1 = SB + (long)(boff + ew1) * DD;
        }

#pragma unroll
        for (int nt = 0; nt < 4; nt++) {
            const int gc = n0 + wn * 32 + nt * 8 + qcol;
            const float* a = acc[mt][nt];
            if (EPI == 0) {
                *(float2*)(C + (long)r0 * ldc + gc) = make_float2(a[0], a[1]);
                *(float2*)(C + (long)r1 * ldc + gc) = make_float2(a[2], a[3]);
            } else if (EPI == 1) {
                float2 b = *(const float2*)(bias + gc);
                *(__half2*)(Cf16 + (long)r0 * ldc + gc) =
                    __floats2half2_rn(fmaxf(a[0] + b.x, 0.f), fmaxf(a[1] + b.y, 0.f));
                *(__half2*)(Cf16 + (long)r1 * ldc + gc) =
                    __floats2half2_rn(fmaxf(a[2] + b.x, 0.f), fmaxf(a[3] + b.y, 0.f));
            } else if (EPI == 3) {
                *(__half2*)(Cf16 + (long)r0 * ldc + gc) = __floats2half2_rn(a[0], a[1]);
                *(__half2*)(Cf16 + (long)r1 * ldc + gc) = __floats2half2_rn(a[2], a[3]);
            } else {
                float2 b  = *(const float2*)(bias + gc);
                float2 s0 = *(const float2*)(sa0 + gc), e0 = *(const float2*)(sb0 + gc);
                float2 s1 = *(const float2*)(sa1 + gc), e1 = *(const float2*)(sb1 + gc);
                float2 o0 = make_float2(fmaxf(a[0] + s0.x + e0.x + b.x, 0.f),
                                        fmaxf(a[1] + s0.y + e0.y + b.y, 0.f));
                float2 o1 = make_float2(fmaxf(a[2] + s1.x + e1.x + b.x, 0.f),
                                        fmaxf(a[3] + s1.y + e1.y + b.y, 0.f));
                *(float2*)(C + (long)r0 * ldc + gc) = o0;
                *(float2*)(C + (long)r1 * ldc + gc) = o1;
            }
        }
    }
}

// ---------------------------------------------------------------------------
extern "C" void kernel_launch(void* const* d_in, const int* in_sizes, int n_in,
                              void* d_out, int out_size) {
    const float* h      = (const float*)d_in[0];
    const int*   span32 = (const int*)d_in[1];
    const float* proj_w = (const float*)d_in[2];
    const float* proj_b = (const float*)d_in[3];
    const float* conv_w = (const float*)d_in[4];
    const float* out_w  = (const float*)d_in[5];
    const float* out_b  = (const float*)d_in[6];
    float*       out    = (float*)d_out;

    __half *hh, *pwh, *owh, *cwth, *ph, *G, *ch;
    float *SA, *SB;
    cudaGetSymbolAddress((void**)&hh,   g_hh);
    cudaGetSymbolAddress((void**)&pwh,  g_pwh);
    cudaGetSymbolAddress((void**)&owh,  g_owh);
    cudaGetSymbolAddress((void**)&cwth, g_cwth);
    cudaGetSymbolAddress((void**)&ph,   g_ph);
    cudaGetSymbolAddress((void**)&G,    g_G);
    cudaGetSymbolAddress((void**)&ch,   g_ch);
    cudaGetSymbolAddress((void**)&SA,   g_SA);
    cudaGetSymbolAddress((void**)&SB,   g_SB);

    cudaFuncSetAttribute((const void*)gemm_mma<0>, cudaFuncAttributeMaxDynamicSharedMemorySize, SMEMB);
    cudaFuncSetAttribute((const void*)gemm_mma<1>, cudaFuncAttributeMaxDynamicSharedMemorySize, SMEMB);
    cudaFuncSetAttribute((const void*)gemm_mma<2>, cudaFuncAttributeMaxDynamicSharedMemorySize, SMEMB);
    cudaFuncSetAttribute((const void*)gemm_mma<3>, cudaFuncAttributeMaxDynamicSharedMemorySize, SMEMB);

    // ---- side streams + fork/join events (host-side handles only; created
    // once; identical captured work every call) ----
    static cudaStream_t s1 = nullptr, s2 = nullptr;
    static cudaEvent_t evFork = nullptr, evJoin = nullptr, evFork2 = nullptr, evCw = nullptr;
    static bool tried = false;
    if (!tried) {
        tried = true;
        if (cudaStreamCreateWithFlags(&s1, cudaStreamNonBlocking) != cudaSuccess) s1 = nullptr;
        if (cudaStreamCreateWithFlags(&s2, cudaStreamNonBlocking) != cudaSuccess) s2 = nullptr;
        if (cudaEventCreateWithFlags(&evFork, cudaEventDisableTiming) != cudaSuccess) evFork = nullptr;
        if (cudaEventCreateWithFlags(&evJoin, cudaEventDisableTiming) != cudaSuccess) evJoin = nullptr;
        if (cudaEventCreateWithFlags(&evFork2, cudaEventDisableTiming) != cudaSuccess) evFork2 = nullptr;
        if (cudaEventCreateWithFlags(&evCw, cudaEventDisableTiming) != cudaSuccess) evCw = nullptr;
    }
    const bool fork  = (s1 && evFork && evJoin);
    const bool fork2 = (s2 && evFork2 && evCw);
    cudaStream_t sB = fork  ? s1 : (cudaStream_t)0;   // branch-B stream
    cudaStream_t sC = fork2 ? s2 : (cudaStream_t)0;   // conv_w transpose stream

    // ---- fork sC immediately (transpose_cw depends only on conv_w) ----
    if (fork2) {
        cudaEventRecord(evFork2, 0);
        cudaStreamWaitEvent(s2, evFork2, 0);
    }
    transpose_cw_kernel<<<(DD * (DD / 2) + 255) / 256, 256, 0, sC>>>(conv_w, (__half2*)cwth);
    if (fork2) cudaEventRecord(evCw, s2);

    // ---- branch-independent prologue (main stream): hh = fp16(h) ----
    tofp16v4_kernel<<<((long)BL * DD / 4 + 255) / 256, 256>>>(
        (const float4*)h, (__half2*)hh, (long)BL * DD / 4);

    if (fork) {
        cudaEventRecord(evFork, 0);
        cudaStreamWaitEvent(s1, evFork, 0);
    }

    // ---- branch A (main): conv path (waits for cwth) ----
    if (fork2) cudaStreamWaitEvent(0, evCw, 0);
    gemm_mma<3><<<dim3(WD / 128, BL / 128), 256, SMEMB>>>(          // G = h @ cwt^T
        hh, DD, cwth, DD, nullptr, G, WD, DD, nullptr, nullptr, nullptr, nullptr,
        nullptr, nullptr, nullptr);
    cumsum_relu_kernel<<<((long)BL * (DD / 2) + 255) / 256, 256>>>( // ch = relu(cumsum(G))
        (const __half2*)G, (__half2*)ch);

    // ---- branch B (s1): span-rep path ----
    detect_idx_kernel<<<1, 256, 0, sB>>>(span32, BB * LL * WW * 2);
    tofp16v4_kernel<<<((long)TWOD * DD / 4 + 255) / 256, 256, 0, sB>>>(
        (const float4*)proj_w, (__half2*)pwh, (long)TWOD * DD / 4);
    tofp16v4_kernel<<<((long)DD * THREED / 4 + 255) / 256, 256, 0, sB>>>(
        (const float4*)out_w, (__half2*)owh, (long)DD * THREED / 4);
    gemm_mma<1><<<dim3(TWOD / 128, BL / 128), 256, SMEMB, sB>>>(    // prelu
        hh, DD, pwh, DD, nullptr, ph, TWOD, DD, proj_b, nullptr, nullptr, nullptr,
        nullptr, nullptr, nullptr);
    gemm_mma<0><<<dim3(DD / 128, BL / 128, 2), 256, SMEMB, sB>>>(   // SA / SB batched
        ph, TWOD, owh, THREED, SA, nullptr, DD, DD, nullptr, nullptr, nullptr, nullptr,
        ph + DD, owh + DD, SB);

    if (fork) {
        cudaEventRecord(evJoin, s1);
        cudaStreamWaitEvent(0, evJoin, 0);
    }

    // ---- final fused GEMM (main) ----
    gemm_mma<2><<<dim3(DD / 128, MOUT / 128), 256, SMEMB>>>(
        ch, DD, owh + TWOD, THREED, out, nullptr, DD, DD,
        out_b, SA, SB, span32, nullptr, nullptr, nullptr);
}

// round 15
// speedup vs baseline: 1.5466x; 1.5466x over previous
#include <cuda_runtime.h>
#include <cuda_fp16.h>
#include <cstdint>

#define BB 4
#define LL 512
#define DD 768
#define WW 12
#define TWOD 1536
#define THREED 2304
#define BL 2048
#define MOUT 24576
#define WD 9216

// ---- scratch (device globals; no allocation allowed) ----
__device__ __align__(16) __half g_hh[(long)BL*DD];                // h fp16
__device__ __align__(16) __half g_pwh[(long)TWOD*DD];             // proj_w fp16
__device__ __align__(16) __half g_owh[(long)DD*THREED];           // out_w fp16
__device__ __align__(16) __half g_cwth[(long)WD*DD];              // conv_w transposed fp16
__device__ __align__(16) __half g_ph[(long)BL*TWOD];              // relu(proj) fp16
__device__ __align__(16) __half g_G[(long)BL*WD];                 // conv contributions fp16
__device__ __align__(16) __half g_ch[(long)MOUT*DD];              // relu(cumsum) fp16
__device__ __align__(16) float  g_SA[(long)BL*DD], g_SB[(long)BL*DD];
__device__ int g_is64;

// ---- PTX helpers (baseline ISA only; valid on compute_103) ----
__device__ __forceinline__ uint32_t smem_u32(const void* p) {
    uint32_t a;
    asm("{ .reg .u64 t; cvta.to.shared.u64 t, %1; cvt.u32.u64 %0, t; }" : "=r"(a) : "l"(p));
    return a;
}
__device__ __forceinline__ void cp16(uint32_t dst, const void* src) {
    asm volatile("cp.async.cg.shared.global [%0], [%1], 16;" :: "r"(dst), "l"(src));
}
#define CP_COMMIT() asm volatile("cp.async.commit_group;" ::: "memory")
#define CP_WAIT1()  asm volatile("cp.async.wait_group 1;" ::: "memory")

#define LDSM4(r, addr) \
    asm volatile("ldmatrix.sync.aligned.m8n8.x4.shared.b16 {%0,%1,%2,%3}, [%4];" \
        : "=r"((r)[0]), "=r"((r)[1]), "=r"((r)[2]), "=r"((r)[3]) : "r"(addr))

#define MMA16816(acc, a, b0, b1) \
    asm volatile("mma.sync.aligned.m16n8k16.row.col.f32.f16.f16.f32 " \
        "{%0,%1,%2,%3}, {%4,%5,%6,%7}, {%8,%9}, {%0,%1,%2,%3};" \
        : "+f"((acc)[0]), "+f"((acc)[1]), "+f"((acc)[2]), "+f"((acc)[3]) \
        : "r"((a)[0]), "r"((a)[1]), "r"((a)[2]), "r"((a)[3]), "r"(b0), "r"(b1))

// ---------------------------------------------------------------------------
__global__ void detect_idx_kernel(const int* __restrict__ p, int nwords) {
    __shared__ int any;
    if (threadIdx.x == 0) any = 0;
    __syncthreads();
    int found = 0;
    for (int i = threadIdx.x; 2 * i + 1 < nwords; i += blockDim.x)
        found |= (p[2 * i + 1] != 0);
    if (found) atomicOr(&any, 1);
    __syncthreads();
    if (threadIdx.x == 0) g_is64 = (any == 0) ? 1 : 0;
}

// fp32 -> fp16, vectorized (n divisible by 4)
__global__ void tofp16v4_kernel(const float4* __restrict__ x, __half2* __restrict__ y, long n4) {
    long i = (long)blockIdx.x * blockDim.x + threadIdx.x;
    if (i >= n4) return;
    float4 v = x[i];
    y[2 * i]     = __floats2half2_rn(v.x, v.y);
    y[2 * i + 1] = __floats2half2_rn(v.z, v.w);
}

// conv_w [o,c,k] -> cwt [k*DD+o][c] fp16, half2 stores
__global__ void transpose_cw_kernel(const float* __restrict__ cw, __half2* __restrict__ th2) {
    int idx = blockIdx.x * blockDim.x + threadIdx.x;   // over DD*DD/2
    if (idx >= DD * (DD / 2)) return;
    int o = idx / (DD / 2), c2 = idx % (DD / 2);
    const float* s0 = cw + ((long)o * DD + 2 * c2) * WW;
    const float* s1 = s0 + WW;
#pragma unroll
    for (int k = 0; k < WW; k++)
        th2[((long)k * DD + o) * (DD / 2) + c2] = __floats2half2_rn(s0[k], s1[k]);
}

// shifted cumsum of G (fp16, fp32 accum) + relu -> fp16, half2 vectorized
__global__ void cumsum_relu_kernel(const __half2* __restrict__ G2, __half2* __restrict__ ch2) {
    long id = (long)blockIdx.x * blockDim.x + threadIdx.x;   // over BL*DD/2
    if (id >= (long)BL * (DD / 2)) return;
    int o2 = (int)(id % (DD / 2));
    int bl = (int)(id / (DD / 2));
    int l  = bl % LL;
    int bt = bl - l;
    float sx = 0.f, sy = 0.f;
#pragma unroll
    for (int k = 0; k < WW; k++) {
        int t = l + k;
        if (t < LL) {
            float2 g = __half22float2(G2[((long)(bt + t) * WW + k) * (DD / 2) + o2]);
            sx += g.x; sy += g.y;
        }
        ch2[((long)bl * WW + k) * (DD / 2) + o2] =
            __floats2half2_rn(fmaxf(sx, 0.f), fmaxf(sy, 0.f));
    }
}

// ---------------------------------------------------------------------------
// fp16 GEMM via mma.sync:  C[m,n] = sum_k A[m,k]*B[n,k]   (fp32 acc)
// CTA tile 128x128, BK=64, 8 warps (2M x 4N), warp tile 64x32.
// 2-stage double buffer, 2 syncs/iter, 64 MMAs per sync interval. 2 CTAs/SM.
// (R13 config — empirically the sweet spot; BK=96 regressed, see R14.)
// EPI: 0=fp32 store, 1=bias+relu->fp16, 2=final fused fp32, 3=plain fp16 store
// blockIdx.z==1 switches to (A2,B2,C2) — used to batch SA/SB in one launch.
#define ROWB 144
#define TILEB (128*ROWB)        // 18432
#define STAGEB (2*TILEB)        // 36864 (A + B)
#define SMEMB (2*STAGEB)        // 73728

template <int EPI>
__global__ __launch_bounds__(256, 2)
void gemm_mma(const __half* __restrict__ Ap, int lda,
              const __half* __restrict__ Bp, int ldb,
              float* __restrict__ Cp, __half* __restrict__ Cf16,
              int ldc, int K,
              const float* __restrict__ bias,
              const float* __restrict__ SA, const float* __restrict__ SB,
              const int* __restrict__ span32,
              const __half* A2, const __half* B2, float* C2) {
    extern __shared__ char smem[];
    const uint32_t sbase = smem_u32(smem);
    const int tid = threadIdx.x, lane = tid & 31, wid = tid >> 5;
    const int wm = wid & 1, wn = wid >> 1;           // 2 x 4 warp grid
    const int m0 = blockIdx.y * 128, n0 = blockIdx.x * 128;
    const int NIT = K >> 6;                          // BK = 64

    const __half* A = Ap;
    const __half* B = Bp;
    float* C = Cp;
    if (blockIdx.z) { A = A2; B = B2; C = C2; }

    const char* gA = (const char*)(A + (long)m0 * lda);
    const char* gB = (const char*)(B + (long)n0 * ldb);
    const long ldaB = (long)lda * 2, ldbB = (long)ldb * 2;

    // per stage: A tile 128 rows x 128B (8 chunks) = 1024 chunks; B same.
    auto issue_load = [&](int it) {
        const int k0b = it << 7;                     // it*64 cols * 2B
        const uint32_t st = sbase + (it & 1) * STAGEB;
#pragma unroll
        for (int i = 0; i < 4; i++) {                // A
            int s = tid + i * 256;
            int r = s >> 3, kc = s & 7;
            cp16(st + r * ROWB + kc * 16, gA + (long)r * ldaB + k0b + kc * 16);
        }
#pragma unroll
        for (int i = 0; i < 4; i++) {                // B
            int s = tid + i * 256;
            int r = s >> 3, kc = s & 7;
            cp16(st + TILEB + r * ROWB + kc * 16, gB + (long)r * ldbB + k0b + kc * 16);
        }
    };

    float acc[4][4][4];
#pragma unroll
    for (int i = 0; i < 4; i++)
#pragma unroll
        for (int j = 0; j < 4; j++)
#pragma unroll
            for (int v = 0; v < 4; v++) acc[i][j][v] = 0.f;

    issue_load(0); CP_COMMIT();

    const uint32_t a_lane_off = (uint32_t)((wm * 64 + (lane & 15)) * ROWB + (lane >> 4) * 16);
    const uint32_t b_lane_off = (uint32_t)((wn * 32 + (lane & 15)) * ROWB + (lane >> 4) * 16);

    for (int it = 0; it < NIT; it++) {
        if (it + 1 < NIT) issue_load(it + 1);
        CP_COMMIT();
        CP_WAIT1();
        __syncthreads();

        const uint32_t st = sbase + (it & 1) * STAGEB;
#pragma unroll
        for (int ks = 0; ks < 4; ks++) {
            uint32_t a[4][4];
#pragma unroll
            for (int mt = 0; mt < 4; mt++)
                LDSM4(a[mt], st + a_lane_off + mt * 16 * ROWB + ks * 32);
            uint32_t b[2][4];
#pragma unroll
            for (int nb = 0; nb < 2; nb++)
                LDSM4(b[nb], st + TILEB + b_lane_off + nb * 16 * ROWB + ks * 32);
#pragma unroll
            for (int mt = 0; mt < 4; mt++)
#pragma unroll
                for (int nt = 0; nt < 4; nt++) {
                    const int nb = nt >> 1, sel = nt & 1;
                    MMA16816(acc[mt][nt], a[mt], b[nb][sel], b[nb][sel + 2]);
                }
        }
        __syncthreads();
    }

    // ---- epilogue ----
    const int qrow = lane >> 2, qcol = (lane & 3) * 2;
    const int is64 = (EPI == 2) ? g_is64 : 0;

#pragma unroll
    for (int mt = 0; mt < 4; mt++) {
        const int r0 = m0 + wm * 64 + mt * 16 + qrow;
        const int r1 = r0 + 8;

        const float *sa0 = nullptr, *sb0 = nullptr, *sa1 = nullptr, *sb1 = nullptr;
        if (EPI == 2) {
            int sw0, ew0, sw1, ew1;
            if (is64) {
                sw0 = span32[(long)r0 * 4]; ew0 = span32[(long)r0 * 4 + 2];
                sw1 = span32[(long)r1 * 4]; ew1 = span32[(long)r1 * 4 + 2];
            } else {
                sw0 = span32[(long)r0 * 2]; ew0 = span32[(long)r0 * 2 + 1];
                sw1 = span32[(long)r1 * 2]; ew1 = span32[(long)r1 * 2 + 1];
            }
            sw0 = min(max(sw0, 0), LL - 1); ew0 = min(max(ew0, 0), LL - 1);
            sw1 = min(max(sw1, 0), LL - 1); ew1 = min(max(ew1, 0), LL - 1);
            int boff = (r0 / (LL * WW)) * LL;   // r0, r1 always in same batch (16 | LL*WW)
            sa0 = SA + (long)(boff + sw0) * DD; sb0 = SB + (long)(boff + ew0) * DD;
            sa1 = SA + (long)(boff + sw1) * DD; sb1 = SB + (long)(boff + ew1) * DD;
        }

#pragma unroll
        for (int nt = 0; nt < 4; nt++) {
            const int gc = n0 + wn * 32 + nt * 8 + qcol;
            const float* a = acc[mt][nt];
            if (EPI == 0) {
                *(float2*)(C + (long)r0 * ldc + gc) = make_float2(a[0], a[1]);
                *(float2*)(C + (long)r1 * ldc + gc) = make_float2(a[2], a[3]);
            } else if (EPI == 1) {
                float2 b = *(const float2*)(bias + gc);
                *(__half2*)(Cf16 + (long)r0 * ldc + gc) =
                    __floats2half2_rn(fmaxf(a[0] + b.x, 0.f), fmaxf(a[1] + b.y, 0.f));
                *(__half2*)(Cf16 + (long)r1 * ldc + gc) =
                    __floats2half2_rn(fmaxf(a[2] + b.x, 0.f), fmaxf(a[3] + b.y, 0.f));
            } else if (EPI == 3) {
                *(__half2*)(Cf16 + (long)r0 * ldc + gc) = __floats2half2_rn(a[0], a[1]);
                *(__half2*)(Cf16 + (long)r1 * ldc + gc) = __floats2half2_rn(a[2], a[3]);
            } else {
                float2 b  = *(const float2*)(bias + gc);
                float2 s0 = *(const float2*)(sa0 + gc), e0 = *(const float2*)(sb0 + gc);
                float2 s1 = *(const float2*)(sa1 + gc), e1 = *(const float2*)(sb1 + gc);
                float2 o0 = make_float2(fmaxf(a[0] + s0.x + e0.x + b.x, 0.f),
                                        fmaxf(a[1] + s0.y + e0.y + b.y, 0.f));
                float2 o1 = make_float2(fmaxf(a[2] + s1.x + e1.x + b.x, 0.f),
                                        fmaxf(a[3] + s1.y + e1.y + b.y, 0.f));
                *(float2*)(C + (long)r0 * ldc + gc) = o0;
                *(float2*)(C + (long)r1 * ldc + gc) = o1;
            }
        }
    }
}

// ---------------------------------------------------------------------------
extern "C" void kernel_launch(void* const* d_in, const int* in_sizes, int n_in,
                              void* d_out, int out_size) {
    const float* h      = (const float*)d_in[0];
    const int*   span32 = (const int*)d_in[1];
    const float* proj_w = (const float*)d_in[2];
    const float* proj_b = (const float*)d_in[3];
    const float* conv_w = (const float*)d_in[4];
    const float* out_w  = (const float*)d_in[5];
    const float* out_b  = (const float*)d_in[6];
    float*       out    = (float*)d_out;

    __half *hh, *pwh, *owh, *cwth, *ph, *G, *ch;
    float *SA, *SB;
    cudaGetSymbolAddress((void**)&hh,   g_hh);
    cudaGetSymbolAddress((void**)&pwh,  g_pwh);
    cudaGetSymbolAddress((void**)&owh,  g_owh);
    cudaGetSymbolAddress((void**)&cwth, g_cwth);
    cudaGetSymbolAddress((void**)&ph,   g_ph);
    cudaGetSymbolAddress((void**)&G,    g_G);
    cudaGetSymbolAddress((void**)&ch,   g_ch);
    cudaGetSymbolAddress((void**)&SA,   g_SA);
    cudaGetSymbolAddress((void**)&SB,   g_SB);

    cudaFuncSetAttribute((const void*)gemm_mma<0>, cudaFuncAttributeMaxDynamicSharedMemorySize, SMEMB);
    cudaFuncSetAttribute((const void*)gemm_mma<1>, cudaFuncAttributeMaxDynamicSharedMemorySize, SMEMB);
    cudaFuncSetAttribute((const void*)gemm_mma<2>, cudaFuncAttributeMaxDynamicSharedMemorySize, SMEMB);
    cudaFuncSetAttribute((const void*)gemm_mma<3>, cudaFuncAttributeMaxDynamicSharedMemorySize, SMEMB);

    // ---- side streams + fork/join events (host-side handles only; created
    // once; identical captured work every call) ----
    static cudaStream_t s1 = nullptr, s2 = nullptr;
    static cudaEvent_t evFork = nullptr, evJoin = nullptr, evFork2 = nullptr, evCw = nullptr;
    static bool tried = false;
    if (!tried) {
        tried = true;
        if (cudaStreamCreateWithFlags(&s1, cudaStreamNonBlocking) != cudaSuccess) s1 = nullptr;
        if (cudaStreamCreateWithFlags(&s2, cudaStreamNonBlocking) != cudaSuccess) s2 = nullptr;
        if (cudaEventCreateWithFlags(&evFork, cudaEventDisableTiming) != cudaSuccess) evFork = nullptr;
        if (cudaEventCreateWithFlags(&evJoin, cudaEventDisableTiming) != cudaSuccess) evJoin = nullptr;
        if (cudaEventCreateWithFlags(&evFork2, cudaEventDisableTiming) != cudaSuccess) evFork2 = nullptr;
        if (cudaEventCreateWithFlags(&evCw, cudaEventDisableTiming) != cudaSuccess) evCw = nullptr;
    }
    const bool fork  = (s1 && evFork && evJoin);
    const bool fork2 = (s2 && evFork2 && evCw);
    cudaStream_t sB = fork  ? s1 : (cudaStream_t)0;   // branch-B stream
    cudaStream_t sC = fork2 ? s2 : (cudaStream_t)0;   // conv_w transpose stream

    // ---- fork sC immediately (transpose_cw depends only on conv_w) ----
    if (fork2) {
        cudaEventRecord(evFork2, 0);
        cudaStreamWaitEvent(s2, evFork2, 0);
    }
    transpose_cw_kernel<<<(DD * (DD / 2) + 255) / 256, 256, 0, sC>>>(conv_w, (__half2*)cwth);
    if (fork2) cudaEventRecord(evCw, s2);

    // ---- branch-independent prologue (main stream): hh = fp16(h) ----
    tofp16v4_kernel<<<((long)BL * DD / 4 + 255) / 256, 256>>>(
        (const float4*)h, (__half2*)hh, (long)BL * DD / 4);

    if (fork) {
        cudaEventRecord(evFork, 0);
        cudaStreamWaitEvent(s1, evFork, 0);
    }

    // ---- branch A (main): conv path (waits for cwth) ----
    if (fork2) cudaStreamWaitEvent(0, evCw, 0);
    gemm_mma<3><<<dim3(WD / 128, BL / 128), 256, SMEMB>>>(          // G = h @ cwt^T
        hh, DD, cwth, DD, nullptr, G, WD, DD, nullptr, nullptr, nullptr, nullptr,
        nullptr, nullptr, nullptr);
    cumsum_relu_kernel<<<((long)BL * (DD / 2) + 255) / 256, 256>>>( // ch = relu(cumsum(G))
        (const __half2*)G, (__half2*)ch);

    // ---- branch B (s1): span-rep path ----
    detect_idx_kernel<<<1, 256, 0, sB>>>(span32, BB * LL * WW * 2);
    tofp16v4_kernel<<<((long)TWOD * DD / 4 + 255) / 256, 256, 0, sB>>>(
        (const float4*)proj_w, (__half2*)pwh, (long)TWOD * DD / 4);
    tofp16v4_kernel<<<((long)DD * THREED / 4 + 255) / 256, 256, 0, sB>>>(
        (const float4*)out_w, (__half2*)owh, (long)DD * THREED / 4);
    gemm_mma<1><<<dim3(TWOD / 128, BL / 128), 256, SMEMB, sB>>>(    // prelu
        hh, DD, pwh, DD, nullptr, ph, TWOD, DD, proj_b, nullptr, nullptr, nullptr,
        nullptr, nullptr, nullptr);
    gemm_mma<0><<<dim3(DD / 128, BL / 128, 2), 256, SMEMB, sB>>>(   // SA / SB batched
        ph, TWOD, owh, THREED, SA, nullptr, DD, DD, nullptr, nullptr, nullptr, nullptr,
        ph + DD, owh + DD, SB);

    if (fork) {
        cudaEventRecord(evJoin, s1);
        cudaStreamWaitEvent(0, evJoin, 0);
    }

    // ---- final fused GEMM (main) ----
    gemm_mma<2><<<dim3(DD / 128, MOUT / 128), 256, SMEMB>>>(
        ch, DD, owh + TWOD, THREED, out, nullptr, DD, DD,
        out_b, SA, SB, span32, nullptr, nullptr, nullptr);
}

// round 16
// speedup vs baseline: 1.5690x; 1.0145x over previous
#include <cuda_runtime.h>
#include <cuda_fp16.h>
#include <cstdint>

#define BB 4
#define LL 512
#define DD 768
#define WW 12
#define TWOD 1536
#define THREED 2304
#define BL 2048
#define MOUT 24576
#define WD 9216

// ---- scratch (device globals; no allocation allowed) ----
__device__ __align__(16) __half g_hh[(long)BL*DD];                // h fp16
__device__ __align__(16) __half g_pwh[(long)TWOD*DD];             // proj_w fp16
__device__ __align__(16) __half g_owh[(long)DD*THREED];           // out_w fp16
__device__ __align__(16) __half g_cwth[(long)WD*DD];              // conv_w transposed fp16
__device__ __align__(16) __half g_ph[(long)BL*TWOD];              // relu(proj) fp16
__device__ __align__(16) __half g_G[(long)BL*WD];                 // conv contributions fp16
__device__ __align__(16) __half g_ch[(long)MOUT*DD];              // relu(cumsum) fp16
__device__ __align__(16) float  g_SA[(long)BL*DD], g_SB[(long)BL*DD];
__device__ int g_is64;

// ---- PTX helpers (baseline ISA only; valid on compute_103) ----
__device__ __forceinline__ uint32_t smem_u32(const void* p) {
    uint32_t a;
    asm("{ .reg .u64 t; cvta.to.shared.u64 t, %1; cvt.u32.u64 %0, t; }" : "=r"(a) : "l"(p));
    return a;
}
__device__ __forceinline__ void cp16(uint32_t dst, const void* src) {
    asm volatile("cp.async.cg.shared.global [%0], [%1], 16;" :: "r"(dst), "l"(src));
}
#define CP_COMMIT() asm volatile("cp.async.commit_group;" ::: "memory")
#define CP_WAIT0()  asm volatile("cp.async.wait_group 0;" ::: "memory")

#define LDSM4(r, addr) \
    asm volatile("ldmatrix.sync.aligned.m8n8.x4.shared.b16 {%0,%1,%2,%3}, [%4];" \
        : "=r"((r)[0]), "=r"((r)[1]), "=r"((r)[2]), "=r"((r)[3]) : "r"(addr))

#define MMA16816(acc, a, b0, b1) \
    asm volatile("mma.sync.aligned.m16n8k16.row.col.f32.f16.f16.f32 " \
        "{%0,%1,%2,%3}, {%4,%5,%6,%7}, {%8,%9}, {%0,%1,%2,%3};" \
        : "+f"((acc)[0]), "+f"((acc)[1]), "+f"((acc)[2]), "+f"((acc)[3]) \
        : "r"((a)[0]), "r"((a)[1]), "r"((a)[2]), "r"((a)[3]), "r"(b0), "r"(b1))

// ---------------------------------------------------------------------------
__global__ void detect_idx_kernel(const int* __restrict__ p, int nwords) {
    __shared__ int any;
    if (threadIdx.x == 0) any = 0;
    __syncthreads();
    int found = 0;
    for (int i = threadIdx.x; 2 * i + 1 < nwords; i += blockDim.x)
        found |= (p[2 * i + 1] != 0);
    if (found) atomicOr(&any, 1);
    __syncthreads();
    if (threadIdx.x == 0) g_is64 = (any == 0) ? 1 : 0;
}

// fp32 -> fp16, vectorized (n divisible by 4)
__global__ void tofp16v4_kernel(const float4* __restrict__ x, __half2* __restrict__ y, long n4) {
    long i = (long)blockIdx.x * blockDim.x + threadIdx.x;
    if (i >= n4) return;
    float4 v = x[i];
    y[2 * i]     = __floats2half2_rn(v.x, v.y);
    y[2 * i + 1] = __floats2half2_rn(v.z, v.w);
}

// conv_w [o,c,k] -> cwt [k*DD+o][c] fp16, half2 stores
__global__ void transpose_cw_kernel(const float* __restrict__ cw, __half2* __restrict__ th2) {
    int idx = blockIdx.x * blockDim.x + threadIdx.x;   // over DD*DD/2
    if (idx >= DD * (DD / 2)) return;
    int o = idx / (DD / 2), c2 = idx % (DD / 2);
    const float* s0 = cw + ((long)o * DD + 2 * c2) * WW;
    const float* s1 = s0 + WW;
#pragma unroll
    for (int k = 0; k < WW; k++)
        th2[((long)k * DD + o) * (DD / 2) + c2] = __floats2half2_rn(s0[k], s1[k]);
}

// shifted cumsum of G (fp16, fp32 accum) + relu -> fp16, half2 vectorized
__global__ void cumsum_relu_kernel(const __half2* __restrict__ G2, __half2* __restrict__ ch2) {
    long id = (long)blockIdx.x * blockDim.x + threadIdx.x;   // over BL*DD/2
    if (id >= (long)BL * (DD / 2)) return;
    int o2 = (int)(id % (DD / 2));
    int bl = (int)(id / (DD / 2));
    int l  = bl % LL;
    int bt = bl - l;
    float sx = 0.f, sy = 0.f;
#pragma unroll
    for (int k = 0; k < WW; k++) {
        int t = l + k;
        if (t < LL) {
            float2 g = __half22float2(G2[((long)(bt + t) * WW + k) * (DD / 2) + o2]);
            sx += g.x; sy += g.y;
        }
        ch2[((long)bl * WW + k) * (DD / 2) + o2] =
            __floats2half2_rn(fmaxf(sx, 0.f), fmaxf(sy, 0.f));
    }
}

// ---------------------------------------------------------------------------
// fp16 GEMM via mma.sync:  C[m,n] = sum_k A[m,k]*B[n,k]   (fp32 acc)
// CTA tile 128x128, BK=64, 8 warps (2M x 4N), warp tile 64x32.
// 2-stage double buffer, ONE sync/iter (load issued after the barrier so the
// overwritten buffer is provably drained). 64 MMAs per sync interval. 2 CTAs/SM.
// EPI: 0=fp32 store, 1=bias+relu->fp16, 2=final fused fp32, 3=plain fp16 store
// blockIdx.z==1 switches to (A2,B2,C2) — used to batch SA/SB in one launch.
#define ROWB 144
#define TILEB (128*ROWB)        // 18432
#define STAGEB (2*TILEB)        // 36864 (A + B)
#define SMEMB (2*STAGEB)        // 73728

template <int EPI>
__global__ __launch_bounds__(256, 2)
void gemm_mma(const __half* __restrict__ Ap, int lda,
              const __half* __restrict__ Bp, int ldb,
              float* __restrict__ Cp, __half* __restrict__ Cf16,
              int ldc, int K,
              const float* __restrict__ bias,
              const float* __restrict__ SA, const float* __restrict__ SB,
              const int* __restrict__ span32,
              const __half* A2, const __half* B2, float* C2) {
    extern __shared__ char smem[];
    const uint32_t sbase = smem_u32(smem);
    const int tid = threadIdx.x, lane = tid & 31, wid = tid >> 5;
    const int wm = wid & 1, wn = wid >> 1;           // 2 x 4 warp grid
    const int m0 = blockIdx.y * 128, n0 = blockIdx.x * 128;
    const int NIT = K >> 6;                          // BK = 64

    const __half* A = Ap;
    const __half* B = Bp;
    float* C = Cp;
    if (blockIdx.z) { A = A2; B = B2; C = C2; }

    const char* gA = (const char*)(A + (long)m0 * lda);
    const char* gB = (const char*)(B + (long)n0 * ldb);
    const long ldaB = (long)lda * 2, ldbB = (long)ldb * 2;

    // per stage: A tile 128 rows x 128B (8 chunks) = 1024 chunks; B same.
    auto issue_load = [&](int it) {
        const int k0b = it << 7;                     // it*64 cols * 2B
        const uint32_t st = sbase + (it & 1) * STAGEB;
#pragma unroll
        for (int i = 0; i < 4; i++) {                // A
            int s = tid + i * 256;
            int r = s >> 3, kc = s & 7;
            cp16(st + r * ROWB + kc * 16, gA + (long)r * ldaB + k0b + kc * 16);
        }
#pragma unroll
        for (int i = 0; i < 4; i++) {                // B
            int s = tid + i * 256;
            int r = s >> 3, kc = s & 7;
            cp16(st + TILEB + r * ROWB + kc * 16, gB + (long)r * ldbB + k0b + kc * 16);
        }
    };

    float acc[4][4][4];
#pragma unroll
    for (int i = 0; i < 4; i++)
#pragma unroll
        for (int j = 0; j < 4; j++)
#pragma unroll
            for (int v = 0; v < 4; v++) acc[i][j][v] = 0.f;

    issue_load(0); CP_COMMIT();

    const uint32_t a_lane_off = (uint32_t)((wm * 64 + (lane & 15)) * ROWB + (lane >> 4) * 16);
    const uint32_t b_lane_off = (uint32_t)((wn * 32 + (lane & 15)) * ROWB + (lane >> 4) * 16);

    for (int it = 0; it < NIT; it++) {
        CP_WAIT0();                 // stage it complete (it+1 not yet issued)
        __syncthreads();            // all warps done reading buf (it+1)&1 (iter it-1)
        if (it + 1 < NIT) { issue_load(it + 1); CP_COMMIT(); }

        const uint32_t st = sbase + (it & 1) * STAGEB;
#pragma unroll
        for (int ks = 0; ks < 4; ks++) {
            uint32_t a[4][4];
#pragma unroll
            for (int mt = 0; mt < 4; mt++)
                LDSM4(a[mt], st + a_lane_off + mt * 16 * ROWB + ks * 32);
            uint32_t b[2][4];
#pragma unroll
            for (int nb = 0; nb < 2; nb++)
                LDSM4(b[nb], st + TILEB + b_lane_off + nb * 16 * ROWB + ks * 32);
#pragma unroll
            for (int mt = 0; mt < 4; mt++)
#pragma unroll
                for (int nt = 0; nt < 4; nt++) {
                    const int nb = nt >> 1, sel = nt & 1;
                    MMA16816(acc[mt][nt], a[mt], b[nb][sel], b[nb][sel + 2]);
                }
        }
    }

    // ---- epilogue ----
    const int qrow = lane >> 2, qcol = (lane & 3) * 2;
    const int is64 = (EPI == 2) ? g_is64 : 0;

#pragma unroll
    for (int mt = 0; mt < 4; mt++) {
        const int r0 = m0 + wm * 64 + mt * 16 + qrow;
        const int r1 = r0 + 8;

        const float *sa0 = nullptr, *sb0 = nullptr, *sa1 = nullptr, *sb1 = nullptr;
        if (EPI == 2) {
            int sw0, ew0, sw1, ew1;
            if (is64) {
                sw0 = span32[(long)r0 * 4]; ew0 = span32[(long)r0 * 4 + 2];
                sw1 = span32[(long)r1 * 4]; ew1 = span32[(long)r1 * 4 + 2];
            } else {
                sw0 = span32[(long)r0 * 2]; ew0 = span32[(long)r0 * 2 + 1];
                sw1 = span32[(long)r1 * 2]; ew1 = span32[(long)r1 * 2 + 1];
            }
            sw0 = min(max(sw0, 0), LL - 1); ew0 = min(max(ew0, 0), LL - 1);
            sw1 = min(max(sw1, 0), LL - 1); ew1 = min(max(ew1, 0), LL - 1);
            int boff = (r0 / (LL * WW)) * LL;   // r0, r1 always in same batch (16 | LL*WW)
            sa0 = SA + (long)(boff + sw0) * DD; sb0 = SB + (long)(boff + ew0) * DD;
            sa1 = SA + (long)(boff + sw1) * DD; sb1 = SB + (long)(boff + ew1) * DD;
        }

#pragma unroll
        for (int nt = 0; nt < 4; nt++) {
            const int gc = n0 + wn * 32 + nt * 8 + qcol;
            const float* a = acc[mt][nt];
            if (EPI == 0) {
                *(float2*)(C + (long)r0 * ldc + gc) = make_float2(a[0], a[1]);
                *(float2*)(C + (long)r1 * ldc + gc) = make_float2(a[2], a[3]);
            } else if (EPI == 1) {
                float2 b = *(const float2*)(bias + gc);
                *(__half2*)(Cf16 + (long)r0 * ldc + gc) =
                    __floats2half2_rn(fmaxf(a[0] + b.x, 0.f), fmaxf(a[1] + b.y, 0.f));
                *(__half2*)(Cf16 + (long)r1 * ldc + gc) =
                    __floats2half2_rn(fmaxf(a[2] + b.x, 0.f), fmaxf(a[3] + b.y, 0.f));
            } else if (EPI == 3) {
                *(__half2*)(Cf16 + (long)r0 * ldc + gc) = __floats2half2_rn(a[0], a[1]);
                *(__half2*)(Cf16 + (long)r1 * ldc + gc) = __floats2half2_rn(a[2], a[3]);
            } else {
                float2 b  = *(const float2*)(bias + gc);
                float2 s0 = *(const float2*)(sa0 + gc), e0 = *(const float2*)(sb0 + gc);
                float2 s1 = *(const float2*)(sa1 + gc), e1 = *(const float2*)(sb1 + gc);
                float2 o0 = make_float2(fmaxf(a[0] + s0.x + e0.x + b.x, 0.f),
                                        fmaxf(a[1] + s0.y + e0.y + b.y, 0.f));
                float2 o1 = make_float2(fmaxf(a[2] + s1.x + e1.x + b.x, 0.f),
                                        fmaxf(a[3] + s1.y + e1.y + b.y, 0.f));
                *(float2*)(C + (long)r0 * ldc + gc) = o0;
                *(float2*)(C + (long)r1 * ldc + gc) = o1;
            }
        }
    }
}

// ---------------------------------------------------------------------------
extern "C" void kernel_launch(void* const* d_in, const int* in_sizes, int n_in,
                              void* d_out, int out_size) {
    const float* h      = (const float*)d_in[0];
    const int*   span32 = (const int*)d_in[1];
    const float* proj_w = (const float*)d_in[2];
    const float* proj_b = (const float*)d_in[3];
    const float* conv_w = (const float*)d_in[4];
    const float* out_w  = (const float*)d_in[5];
    const float* out_b  = (const float*)d_in[6];
    float*       out    = (float*)d_out;

    __half *hh, *pwh, *owh, *cwth, *ph, *G, *ch;
    float *SA, *SB;
    cudaGetSymbolAddress((void**)&hh,   g_hh);
    cudaGetSymbolAddress((void**)&pwh,  g_pwh);
    cudaGetSymbolAddress((void**)&owh,  g_owh);
    cudaGetSymbolAddress((void**)&cwth, g_cwth);
    cudaGetSymbolAddress((void**)&ph,   g_ph);
    cudaGetSymbolAddress((void**)&G,    g_G);
    cudaGetSymbolAddress((void**)&ch,   g_ch);
    cudaGetSymbolAddress((void**)&SA,   g_SA);
    cudaGetSymbolAddress((void**)&SB,   g_SB);

    cudaFuncSetAttribute((const void*)gemm_mma<0>, cudaFuncAttributeMaxDynamicSharedMemorySize, SMEMB);
    cudaFuncSetAttribute((const void*)gemm_mma<1>, cudaFuncAttributeMaxDynamicSharedMemorySize, SMEMB);
    cudaFuncSetAttribute((const void*)gemm_mma<2>, cudaFuncAttributeMaxDynamicSharedMemorySize, SMEMB);
    cudaFuncSetAttribute((const void*)gemm_mma<3>, cudaFuncAttributeMaxDynamicSharedMemorySize, SMEMB);

    // ---- side streams + fork/join events (host-side handles only; created
    // once; identical captured work every call) ----
    static cudaStream_t s1 = nullptr, s2 = nullptr;
    static cudaEvent_t evFork = nullptr, evJoin = nullptr, evFork2 = nullptr, evCw = nullptr;
    static bool tried = false;
    if (!tried) {
        tried = true;
        if (cudaStreamCreateWithFlags(&s1, cudaStreamNonBlocking) != cudaSuccess) s1 = nullptr;
        if (cudaStreamCreateWithFlags(&s2, cudaStreamNonBlocking) != cudaSuccess) s2 = nullptr;
        if (cudaEventCreateWithFlags(&evFork, cudaEventDisableTiming) != cudaSuccess) evFork = nullptr;
        if (cudaEventCreateWithFlags(&evJoin, cudaEventDisableTiming) != cudaSuccess) evJoin = nullptr;
        if (cudaEventCreateWithFlags(&evFork2, cudaEventDisableTiming) != cudaSuccess) evFork2 = nullptr;
        if (cudaEventCreateWithFlags(&evCw, cudaEventDisableTiming) != cudaSuccess) evCw = nullptr;
    }
    const bool fork  = (s1 && evFork && evJoin);
    const bool fork2 = (s2 && evFork2 && evCw);
    cudaStream_t sB = fork  ? s1 : (cudaStream_t)0;   // branch-B stream
    cudaStream_t sC = fork2 ? s2 : (cudaStream_t)0;   // conv_w transpose stream

    // ---- fork sC immediately (transpose_cw depends only on conv_w) ----
    if (fork2) {
        cudaEventRecord(evFork2, 0);
        cudaStreamWaitEvent(s2, evFork2, 0);
    }
    transpose_cw_kernel<<<(DD * (DD / 2) + 255) / 256, 256, 0, sC>>>(conv_w, (__half2*)cwth);
    if (fork2) cudaEventRecord(evCw, s2);

    // ---- branch-independent prologue (main stream): hh = fp16(h) ----
    tofp16v4_kernel<<<((long)BL * DD / 4 + 255) / 256, 256>>>(
        (const float4*)h, (__half2*)hh, (long)BL * DD / 4);

    if (fork) {
        cudaEventRecord(evFork, 0);
        cudaStreamWaitEvent(s1, evFork, 0);
    }

    // ---- branch A (main): conv path (waits for cwth) ----
    if (fork2) cudaStreamWaitEvent(0, evCw, 0);
    gemm_mma<3><<<dim3(WD / 128, BL / 128), 256, SMEMB>>>(          // G = h @ cwt^T
        hh, DD, cwth, DD, nullptr, G, WD, DD, nullptr, nullptr, nullptr, nullptr,
        nullptr, nullptr, nullptr);
    cumsum_relu_kernel<<<((long)BL * (DD / 2) + 255) / 256, 256>>>( // ch = relu(cumsum(G))
        (const __half2*)G, (__half2*)ch);

    // ---- branch B (s1): span-rep path ----
    detect_idx_kernel<<<1, 256, 0, sB>>>(span32, BB * LL * WW * 2);
    tofp16v4_kernel<<<((long)TWOD * DD / 4 + 255) / 256, 256, 0, sB>>>(
        (const float4*)proj_w, (__half2*)pwh, (long)TWOD * DD / 4);
    tofp16v4_kernel<<<((long)DD * THREED / 4 + 255) / 256, 256, 0, sB>>>(
        (const float4*)out_w, (__half2*)owh, (long)DD * THREED / 4);
    gemm_mma<1><<<dim3(TWOD / 128, BL / 128), 256, SMEMB, sB>>>(    // prelu
        hh, DD, pwh, DD, nullptr, ph, TWOD, DD, proj_b, nullptr, nullptr, nullptr,
        nullptr, nullptr, nullptr);
    gemm_mma<0><<<dim3(DD / 128, BL / 128, 2), 256, SMEMB, sB>>>(   // SA / SB batched
        ph, TWOD, owh, THREED, SA, nullptr, DD, DD, nullptr, nullptr, nullptr, nullptr,
        ph + DD, owh + DD, SB);

    if (fork) {
        cudaEventRecord(evJoin, s1);
        cudaStreamWaitEvent(0, evJoin, 0);
    }

    // ---- final fused GEMM (main) ----
    gemm_mma<2><<<dim3(DD / 128, MOUT / 128), 256, SMEMB>>>(
        ch, DD, owh + TWOD, THREED, out, nullptr, DD, DD,
        out_b, SA, SB, span32, nullptr, nullptr, nullptr);
}

// round 17
// speedup vs baseline: 1.6165x; 1.0303x over previous
#include <cuda_runtime.h>
#include <cuda_fp16.h>
#include <cstdint>

#define BB 4
#define LL 512
#define DD 768
#define WW 12
#define TWOD 1536
#define THREED 2304
#define BL 2048
#define MOUT 24576
#define WD 9216

// ---- scratch (device globals; no allocation allowed) ----
__device__ __align__(16) __half g_hh[(long)BL*DD];                // h fp16
__device__ __align__(16) __half g_pwh[(long)TWOD*DD];             // proj_w fp16
__device__ __align__(16) __half g_owh[(long)DD*THREED];           // out_w fp16
__device__ __align__(16) __half g_cwth[(long)WD*DD];              // conv_w transposed fp16
__device__ __align__(16) __half g_ph[(long)BL*TWOD];              // relu(proj) fp16
__device__ __align__(16) __half g_G[(long)BL*WD];                 // conv contributions fp16
__device__ __align__(16) __half g_ch[(long)MOUT*DD];              // relu(cumsum) fp16
__device__ __align__(16) float  g_SA[(long)BL*DD], g_SB[(long)BL*DD];
__device__ int g_is64;

// ---- PTX helpers (baseline ISA only; valid on compute_103) ----
__device__ __forceinline__ uint32_t smem_u32(const void* p) {
    uint32_t a;
    asm("{ .reg .u64 t; cvta.to.shared.u64 t, %1; cvt.u32.u64 %0, t; }" : "=r"(a) : "l"(p));
    return a;
}
__device__ __forceinline__ void cp16(uint32_t dst, const void* src) {
    asm volatile("cp.async.cg.shared.global [%0], [%1], 16;" :: "r"(dst), "l"(src));
}
#define CP_COMMIT() asm volatile("cp.async.commit_group;" ::: "memory")
#define CP_WAIT0()  asm volatile("cp.async.wait_group 0;" ::: "memory")

#define LDSM4(r, addr) \
    asm volatile("ldmatrix.sync.aligned.m8n8.x4.shared.b16 {%0,%1,%2,%3}, [%4];" \
        : "=r"((r)[0]), "=r"((r)[1]), "=r"((r)[2]), "=r"((r)[3]) : "r"(addr))

#define MMA16816(acc, a, b0, b1) \
    asm volatile("mma.sync.aligned.m16n8k16.row.col.f32.f16.f16.f32 " \
        "{%0,%1,%2,%3}, {%4,%5,%6,%7}, {%8,%9}, {%0,%1,%2,%3};" \
        : "+f"((acc)[0]), "+f"((acc)[1]), "+f"((acc)[2]), "+f"((acc)[3]) \
        : "r"((a)[0]), "r"((a)[1]), "r"((a)[2]), "r"((a)[3]), "r"(b0), "r"(b1))

// ---------------------------------------------------------------------------
__global__ void detect_idx_kernel(const int* __restrict__ p, int nwords) {
    __shared__ int any;
    if (threadIdx.x == 0) any = 0;
    __syncthreads();
    int found = 0;
    for (int i = threadIdx.x; 2 * i + 1 < nwords; i += blockDim.x)
        found |= (p[2 * i + 1] != 0);
    if (found) atomicOr(&any, 1);
    __syncthreads();
    if (threadIdx.x == 0) g_is64 = (any == 0) ? 1 : 0;
}

// fp32 -> fp16, vectorized (n divisible by 4)
__global__ void tofp16v4_kernel(const float4* __restrict__ x, __half2* __restrict__ y, long n4) {
    long i = (long)blockIdx.x * blockDim.x + threadIdx.x;
    if (i >= n4) return;
    float4 v = x[i];
    y[2 * i]     = __floats2half2_rn(v.x, v.y);
    y[2 * i + 1] = __floats2half2_rn(v.z, v.w);
}

// two-tensor fp32 -> fp16 convert in one launch (branch-B weights)
__global__ void tofp16v4x2_kernel(const float4* __restrict__ x1, __half2* __restrict__ y1, long n41,
                                  const float4* __restrict__ x2, __half2* __restrict__ y2, long n42) {
    long i = (long)blockIdx.x * blockDim.x + threadIdx.x;
    const float4* x; __half2* y; long j;
    if (i < n41) { x = x1; y = y1; j = i; }
    else if (i < n41 + n42) { x = x2; y = y2; j = i - n41; }
    else return;
    float4 v = x[j];
    y[2 * j]     = __floats2half2_rn(v.x, v.y);
    y[2 * j + 1] = __floats2half2_rn(v.z, v.w);
}

// conv_w [o,c,k] -> cwt [k*DD+o][c] fp16, half2 stores
__global__ void transpose_cw_kernel(const float* __restrict__ cw, __half2* __restrict__ th2) {
    int idx = blockIdx.x * blockDim.x + threadIdx.x;   // over DD*DD/2
    if (idx >= DD * (DD / 2)) return;
    int o = idx / (DD / 2), c2 = idx % (DD / 2);
    const float* s0 = cw + ((long)o * DD + 2 * c2) * WW;
    const float* s1 = s0 + WW;
#pragma unroll
    for (int k = 0; k < WW; k++)
        th2[((long)k * DD + o) * (DD / 2) + c2] = __floats2half2_rn(s0[k], s1[k]);
}

// shifted cumsum of G (fp16, fp32 accum) + relu -> fp16, half2 vectorized
__global__ void cumsum_relu_kernel(const __half2* __restrict__ G2, __half2* __restrict__ ch2) {
    long id = (long)blockIdx.x * blockDim.x + threadIdx.x;   // over BL*DD/2
    if (id >= (long)BL * (DD / 2)) return;
    int o2 = (int)(id % (DD / 2));
    int bl = (int)(id / (DD / 2));
    int l  = bl % LL;
    int bt = bl - l;
    float sx = 0.f, sy = 0.f;
#pragma unroll
    for (int k = 0; k < WW; k++) {
        int t = l + k;
        if (t < LL) {
            float2 g = __half22float2(G2[((long)(bt + t) * WW + k) * (DD / 2) + o2]);
            sx += g.x; sy += g.y;
        }
        ch2[((long)bl * WW + k) * (DD / 2) + o2] =
            __floats2half2_rn(fmaxf(sx, 0.f), fmaxf(sy, 0.f));
    }
}

// ---------------------------------------------------------------------------
// fp16 GEMM via mma.sync:  C[m,n] = sum_k A[m,k]*B[n,k]   (fp32 acc)
// CTA tile 128x128, BK=64, 8 warps (2M x 4N), warp tile 64x32.
// 2-stage double buffer, ONE sync/iter; next-stage cp.async issued AFTER the
// first ks sub-step so the tensor pipe restarts immediately post-barrier.
// 64 MMAs per sync interval. 2 CTAs/SM.
// EPI: 0=fp32 store, 1=bias+relu->fp16, 2=final fused fp32, 3=plain fp16 store
// blockIdx.z==1 switches to (A2,B2,C2) — used to batch SA/SB in one launch.
#define ROWB 144
#define TILEB (128*ROWB)        // 18432
#define STAGEB (2*TILEB)        // 36864 (A + B)
#define SMEMB (2*STAGEB)        // 73728

template <int EPI>
__global__ __launch_bounds__(256, 2)
void gemm_mma(const __half* __restrict__ Ap, int lda,
              const __half* __restrict__ Bp, int ldb,
              float* __restrict__ Cp, __half* __restrict__ Cf16,
              int ldc, int K,
              const float* __restrict__ bias,
              const float* __restrict__ SA, const float* __restrict__ SB,
              const int* __restrict__ span32,
              const __half* A2, const __half* B2, float* C2) {
    extern __shared__ char smem[];
    const uint32_t sbase = smem_u32(smem);
    const int tid = threadIdx.x, lane = tid & 31, wid = tid >> 5;
    const int wm = wid & 1, wn = wid >> 1;           // 2 x 4 warp grid
    const int m0 = blockIdx.y * 128, n0 = blockIdx.x * 128;
    const int NIT = K >> 6;                          // BK = 64

    const __half* A = Ap;
    const __half* B = Bp;
    float* C = Cp;
    if (blockIdx.z) { A = A2; B = B2; C = C2; }

    const char* gA = (const char*)(A + (long)m0 * lda);
    const char* gB = (const char*)(B + (long)n0 * ldb);
    const long ldaB = (long)lda * 2, ldbB = (long)ldb * 2;

    // per stage: A tile 128 rows x 128B (8 chunks) = 1024 chunks; B same.
    auto issue_load = [&](int it) {
        const int k0b = it << 7;                     // it*64 cols * 2B
        const uint32_t st = sbase + (it & 1) * STAGEB;
#pragma unroll
        for (int i = 0; i < 4; i++) {                // A
            int s = tid + i * 256;
            int r = s >> 3, kc = s & 7;
            cp16(st + r * ROWB + kc * 16, gA + (long)r * ldaB + k0b + kc * 16);
        }
#pragma unroll
        for (int i = 0; i < 4; i++) {                // B
            int s = tid + i * 256;
            int r = s >> 3, kc = s & 7;
            cp16(st + TILEB + r * ROWB + kc * 16, gB + (long)r * ldbB + k0b + kc * 16);
        }
    };

    float acc[4][4][4];
#pragma unroll
    for (int i = 0; i < 4; i++)
#pragma unroll
        for (int j = 0; j < 4; j++)
#pragma unroll
            for (int v = 0; v < 4; v++) acc[i][j][v] = 0.f;

    issue_load(0); CP_COMMIT();

    const uint32_t a_lane_off = (uint32_t)((wm * 64 + (lane & 15)) * ROWB + (lane >> 4) * 16);
    const uint32_t b_lane_off = (uint32_t)((wn * 32 + (lane & 15)) * ROWB + (lane >> 4) * 16);

    for (int it = 0; it < NIT; it++) {
        CP_WAIT0();                 // stage it complete (it+1 not yet issued)
        __syncthreads();            // all warps done reading buf (it+1)&1 (iter it-1)

        const uint32_t st = sbase + (it & 1) * STAGEB;
#pragma unroll
        for (int ks = 0; ks < 4; ks++) {
            uint32_t a[4][4];
#pragma unroll
            for (int mt = 0; mt < 4; mt++)
                LDSM4(a[mt], st + a_lane_off + mt * 16 * ROWB + ks * 32);
            uint32_t b[2][4];
#pragma unroll
            for (int nb = 0; nb < 2; nb++)
                LDSM4(b[nb], st + TILEB + b_lane_off + nb * 16 * ROWB + ks * 32);
#pragma unroll
            for (int mt = 0; mt < 4; mt++)
#pragma unroll
                for (int nt = 0; nt < 4; nt++) {
                    const int nb2 = nt >> 1, sel = nt & 1;
                    MMA16816(acc[mt][nt], a[mt], b[nb2][sel], b[nb2][sel + 2]);
                }
            // prefetch next stage after the first sub-step: tensor pipe is
            // already busy, and the load still has ~3 sub-steps of slack.
            if (ks == 0 && it + 1 < NIT) { issue_load(it + 1); CP_COMMIT(); }
        }
    }

    // ---- epilogue ----
    const int qrow = lane >> 2, qcol = (lane & 3) * 2;
    const int is64 = (EPI == 2) ? g_is64 : 0;

#pragma unroll
    for (int mt = 0; mt < 4; mt++) {
        const int r0 = m0 + wm * 64 + mt * 16 + qrow;
        const int r1 = r0 + 8;

        const float *sa0 = nullptr, *sb0 = nullptr, *sa1 = nullptr, *sb1 = nullptr;
        if (EPI == 2) {
            int sw0, ew0, sw1, ew1;
            if (is64) {
                sw0 = span32[(long)r0 * 4]; ew0 = span32[(long)r0 * 4 + 2];
                sw1 = span32[(long)r1 * 4]; ew1 = span32[(long)r1 * 4 + 2];
            } else {
                sw0 = span32[(long)r0 * 2]; ew0 = span32[(long)r0 * 2 + 1];
                sw1 = span32[(long)r1 * 2]; ew1 = span32[(long)r1 * 2 + 1];
            }
            sw0 = min(max(sw0, 0), LL - 1); ew0 = min(max(ew0, 0), LL - 1);
            sw1 = min(max(sw1, 0), LL - 1); ew1 = min(max(ew1, 0), LL - 1);
            int boff = (r0 / (LL * WW)) * LL;   // r0, r1 always in same batch (16 | LL*WW)
            sa0 = SA + (long)(boff + sw0) * DD; sb0 = SB + (long)(boff + ew0) * DD;
            sa1 = SA + (long)(boff + sw1) * DD; sb1 = SB + (long)(boff + ew1) * DD;
        }

#pragma unroll
        for (int nt = 0; nt < 4; nt++) {
            const int gc = n0 + wn * 32 + nt * 8 + qcol;
            const float* a = acc[mt][nt];
            if (EPI == 0) {
                *(float2*)(C + (long)r0 * ldc + gc) = make_float2(a[0], a[1]);
                *(float2*)(C + (long)r1 * ldc + gc) = make_float2(a[2], a[3]);
            } else if (EPI == 1) {
                float2 b = *(const float2*)(bias + gc);
                *(__half2*)(Cf16 + (long)r0 * ldc + gc) =
                    __floats2half2_rn(fmaxf(a[0] + b.x, 0.f), fmaxf(a[1] + b.y, 0.f));
                *(__half2*)(Cf16 + (long)r1 * ldc + gc) =
                    __floats2half2_rn(fmaxf(a[2] + b.x, 0.f), fmaxf(a[3] + b.y, 0.f));
            } else if (EPI == 3) {
                *(__half2*)(Cf16 + (long)r0 * ldc + gc) = __floats2half2_rn(a[0], a[1]);
                *(__half2*)(Cf16 + (long)r1 * ldc + gc) = __floats2half2_rn(a[2], a[3]);
            } else {
                float2 b  = *(const float2*)(bias + gc);
                float2 s0 = *(const float2*)(sa0 + gc), e0 = *(const float2*)(sb0 + gc);
                float2 s1 = *(const float2*)(sa1 + gc), e1 = *(const float2*)(sb1 + gc);
                float2 o0 = make_float2(fmaxf(a[0] + s0.x + e0.x + b.x, 0.f),
                                        fmaxf(a[1] + s0.y + e0.y + b.y, 0.f));
                float2 o1 = make_float2(fmaxf(a[2] + s1.x + e1.x + b.x, 0.f),
                                        fmaxf(a[3] + s1.y + e1.y + b.y, 0.f));
                *(float2*)(C + (long)r0 * ldc + gc) = o0;
                *(float2*)(C + (long)r1 * ldc + gc) = o1;
            }
        }
    }
}

// ---------------------------------------------------------------------------
extern "C" void kernel_launch(void* const* d_in, const int* in_sizes, int n_in,
                              void* d_out, int out_size) {
    const float* h      = (const float*)d_in[0];
    const int*   span32 = (const int*)d_in[1];
    const float* proj_w = (const float*)d_in[2];
    const float* proj_b = (const float*)d_in[3];
    const float* conv_w = (const float*)d_in[4];
    const float* out_w  = (const float*)d_in[5];
    const float* out_b  = (const float*)d_in[6];
    float*       out    = (float*)d_out;

    __half *hh, *pwh, *owh, *cwth, *ph, *G, *ch;
    float *SA, *SB;
    cudaGetSymbolAddress((void**)&hh,   g_hh);
    cudaGetSymbolAddress((void**)&pwh,  g_pwh);
    cudaGetSymbolAddress((void**)&owh,  g_owh);
    cudaGetSymbolAddress((void**)&cwth, g_cwth);
    cudaGetSymbolAddress((void**)&ph,   g_ph);
    cudaGetSymbolAddress((void**)&G,    g_G);
    cudaGetSymbolAddress((void**)&ch,   g_ch);
    cudaGetSymbolAddress((void**)&SA,   g_SA);
    cudaGetSymbolAddress((void**)&SB,   g_SB);

    cudaFuncSetAttribute((const void*)gemm_mma<0>, cudaFuncAttributeMaxDynamicSharedMemorySize, SMEMB);
    cudaFuncSetAttribute((const void*)gemm_mma<1>, cudaFuncAttributeMaxDynamicSharedMemorySize, SMEMB);
    cudaFuncSetAttribute((const void*)gemm_mma<2>, cudaFuncAttributeMaxDynamicSharedMemorySize, SMEMB);
    cudaFuncSetAttribute((const void*)gemm_mma<3>, cudaFuncAttributeMaxDynamicSharedMemorySize, SMEMB);

    // ---- side streams + fork/join events (host-side handles only; created
    // once; identical captured work every call) ----
    static cudaStream_t s1 = nullptr, s2 = nullptr;
    static cudaEvent_t evFork = nullptr, evJoin = nullptr, evFork2 = nullptr, evCw = nullptr;
    static bool tried = false;
    if (!tried) {
        tried = true;
        if (cudaStreamCreateWithFlags(&s1, cudaStreamNonBlocking) != cudaSuccess) s1 = nullptr;
        if (cudaStreamCreateWithFlags(&s2, cudaStreamNonBlocking) != cudaSuccess) s2 = nullptr;
        if (cudaEventCreateWithFlags(&evFork, cudaEventDisableTiming) != cudaSuccess) evFork = nullptr;
        if (cudaEventCreateWithFlags(&evJoin, cudaEventDisableTiming) != cudaSuccess) evJoin = nullptr;
        if (cudaEventCreateWithFlags(&evFork2, cudaEventDisableTiming) != cudaSuccess) evFork2 = nullptr;
        if (cudaEventCreateWithFlags(&evCw, cudaEventDisableTiming) != cudaSuccess) evCw = nullptr;
    }
    const bool fork  = (s1 && evFork && evJoin);
    const bool fork2 = (s2 && evFork2 && evCw);
    cudaStream_t sB = fork  ? s1 : (cudaStream_t)0;   // branch-B stream
    cudaStream_t sC = fork2 ? s2 : (cudaStream_t)0;   // conv_w transpose stream

    // ---- fork sC immediately (transpose_cw depends only on conv_w) ----
    if (fork2) {
        cudaEventRecord(evFork2, 0);
        cudaStreamWaitEvent(s2, evFork2, 0);
    }
    transpose_cw_kernel<<<(DD * (DD / 2) + 255) / 256, 256, 0, sC>>>(conv_w, (__half2*)cwth);
    if (fork2) cudaEventRecord(evCw, s2);

    // ---- branch-independent prologue (main stream): hh = fp16(h) ----
    tofp16v4_kernel<<<((long)BL * DD / 4 + 255) / 256, 256>>>(
        (const float4*)h, (__half2*)hh, (long)BL * DD / 4);

    if (fork) {
        cudaEventRecord(evFork, 0);
        cudaStreamWaitEvent(s1, evFork, 0);
    }

    // ---- branch A (main): conv path (waits for cwth) ----
    if (fork2) cudaStreamWaitEvent(0, evCw, 0);
    gemm_mma<3><<<dim3(WD / 128, BL / 128), 256, SMEMB>>>(          // G = h @ cwt^T
        hh, DD, cwth, DD, nullptr, G, WD, DD, nullptr, nullptr, nullptr, nullptr,
        nullptr, nullptr, nullptr);
    cumsum_relu_kernel<<<((long)BL * (DD / 2) + 255) / 256, 256>>>( // ch = relu(cumsum(G))
        (const __half2*)G, (__half2*)ch);

    // ---- branch B (s1): span-rep path ----
    detect_idx_kernel<<<1, 256, 0, sB>>>(span32, BB * LL * WW * 2);
    {
        long n41 = (long)TWOD * DD / 4, n42 = (long)DD * THREED / 4;
        tofp16v4x2_kernel<<<(n41 + n42 + 255) / 256, 256, 0, sB>>>(
            (const float4*)proj_w, (__half2*)pwh, n41,
            (const float4*)out_w,  (__half2*)owh, n42);
    }
    gemm_mma<1><<<dim3(TWOD / 128, BL / 128), 256, SMEMB, sB>>>(    // prelu
        hh, DD, pwh, DD, nullptr, ph, TWOD, DD, proj_b, nullptr, nullptr, nullptr,
        nullptr, nullptr, nullptr);
    gemm_mma<0><<<dim3(DD / 128, BL / 128, 2), 256, SMEMB, sB>>>(   // SA / SB batched
        ph, TWOD, owh, THREED, SA, nullptr, DD, DD, nullptr, nullptr, nullptr, nullptr,
        ph + DD, owh + DD, SB);

    if (fork) {
        cudaEventRecord(evJoin, s1);
        cudaStreamWaitEvent(0, evJoin, 0);
    }

    // ---- final fused GEMM (main) ----
    gemm_mma<2><<<dim3(DD / 128, MOUT / 128), 256, SMEMB>>>(
        ch, DD, owh + TWOD, THREED, out, nullptr, DD, DD,
        out_b, SA, SB, span32, nullptr, nullptr, nullptr);
}